// round 3
// baseline (speedup 1.0000x reference)
#include <cuda_runtime.h>
#include <math.h>

#define C 64
#define P (512 * 512)          // 262144 pixels
#define K 20
#define NUM_CLASSES 11
#define EPS 1e-8f

#define NBLOCK 512
#define PIX_PER_BLOCK (P / NBLOCK)   // 512
#define TILE 64
#define NTILE (PIX_PER_BLOCK / TILE) // 8
#define PAD 66                        // even -> 8B-aligned pixel pairs

// Per-block partials: sum1[20][64] | usum[20][64] | counts[20] | sq[20]  = 2600 floats
#define PART_STRIDE 2600
#define OFF_SUM1 0
#define OFF_USUM 1280
#define OFF_CNT 2560
#define OFF_SQ 2580

static __device__ float g_part[NBLOCK * PART_STRIDE];
static __device__ float g_red[PART_STRIDE];

typedef unsigned long long u64;

__device__ __forceinline__ u64 pk(float lo, float hi) {
    u64 r;
    asm("mov.b64 %0, {%1, %2};" : "=l"(r) : "f"(lo), "f"(hi));
    return r;
}
__device__ __forceinline__ void upk(float& lo, float& hi, u64 v) {
    asm("mov.b64 {%0, %1}, %2;" : "=f"(lo), "=f"(hi) : "l"(v));
}
#define FMA2(acc, m, v) asm("fma.rn.f32x2 %0, %1, %2, %0;" : "+l"(acc) : "l"(m), "l"(v))
#define ADD2(acc, a)    asm("add.rn.f32x2 %0, %0, %1;"     : "+l"(acc) : "l"(a))

// ---------------------------------------------------------------------------
// Main pass. 256 threads = 64 channels (c = tid&63) x 4 k-groups (kg = tid>>6).
// Thread accumulates instances k = kg + 4j, j = 0..4, over pixel PAIRS with
// packed f32x2 FMA. Mask bits expanded once per tile into s_mf (packed pairs).
// ---------------------------------------------------------------------------
__global__ void __launch_bounds__(256, 4)
main_pass(const float* __restrict__ v1g,
          const float* __restrict__ v2g,
          const int* __restrict__ masks)
{
    __shared__ __align__(16) float s_v1[C * PAD];
    __shared__ __align__(16) float s_v2[C * PAD];
    __shared__ __align__(16) float s_mf[4 * 32 * 12];  // [kg][pair][j0p0,j0p1,...,j4p1,pad,pad]
    __shared__ float s_p1[4 * TILE];
    __shared__ float s_p2[4 * TILE];
    __shared__ __align__(16) float s_s1[TILE];
    __shared__ float s_inv[TILE];
    __shared__ int   s_mb[TILE];

    const int tid = threadIdx.x;
    const int c   = tid & 63;
    const int kg  = tid >> 6;
    const int p_l = tid & 63;
    const int q_l = tid >> 6;

    u64 acc1[5] = {0, 0, 0, 0, 0};
    u64 acc2[5] = {0, 0, 0, 0, 0};
    u64 cnt2 = 0, sq2 = 0;     // only meaningful for tid < 20

    const int p0_blk = blockIdx.x * PIX_PER_BLOCK;

    for (int t = 0; t < NTILE; ++t) {
        const int p0 = p0_blk + t * TILE;
        __syncthreads();

        // ---- Phase A: stage tiles (coalesced float4) ----------------------
#pragma unroll
        for (int i = 0; i < 4; ++i) {
            int idx = tid + i * 256;
            int cc = idx >> 4;
            int pp = (idx & 15) * 4;
            float4 a = *(const float4*)&v1g[(size_t)cc * P + p0 + pp];
            float4 b = *(const float4*)&v2g[(size_t)cc * P + p0 + pp];
            float* d1 = &s_v1[cc * PAD + pp];
            float* d2 = &s_v2[cc * PAD + pp];
            d1[0] = a.x; d1[1] = a.y; d1[2] = a.z; d1[3] = a.w;
            d2[0] = b.x; d2[1] = b.y; d2[2] = b.z; d2[3] = b.w;
        }
        if (tid < TILE) {
            int mb = 0;
#pragma unroll
            for (int k = 0; k < K; ++k) {
                int m = masks[(size_t)k * P + p0 + tid];
                mb |= (m & 1) << k;
            }
            s_mb[tid] = mb;
        }
        __syncthreads();

        // ---- Phase B1: norm partials + mask-float build -------------------
        {
            float s1 = 0.f, s2 = 0.f;
            const int cbase = q_l * 16;
#pragma unroll
            for (int cc = 0; cc < 16; ++cc) {
                float a = s_v1[(cbase + cc) * PAD + p_l];
                float b = s_v2[(cbase + cc) * PAD + p_l];
                s1 = fmaf(a, a, s1);
                s2 = fmaf(b, b, s2);
            }
            s_p1[q_l * TILE + p_l] = s1;
            s_p2[q_l * TILE + p_l] = s2;
        }
        // mask floats: 4 kg * 32 pairs * 10 slots = 1280 entries, 5 per thread
        {
            const int mykg = tid >> 6;       // 64 threads per kg
            const int loc  = tid & 63;
#pragma unroll
            for (int r = 0; r < 5; ++r) {
                int e    = loc + 64 * r;     // 0..319
                int pair = e / 10;
                int slot = e - pair * 10;    // 2*j + which
                int j    = slot >> 1;
                int wh   = slot & 1;
                int p    = 2 * pair + wh;
                int k    = mykg + 4 * j;
                s_mf[(mykg * 32 + pair) * 12 + slot] =
                    (float)((s_mb[p] >> k) & 1);
            }
        }
        __syncthreads();

        // ---- Phase B2: combine norms (64 threads) -------------------------
        if (tid < TILE) {
            float s1 = s_p1[tid] + s_p1[TILE + tid] + s_p1[2 * TILE + tid] + s_p1[3 * TILE + tid];
            float s2 = s_p2[tid] + s_p2[TILE + tid] + s_p2[2 * TILE + tid] + s_p2[3 * TILE + tid];
            s_s1[tid]  = s1;
            s_inv[tid] = 1.0f / fmaxf(sqrtf(s2), EPS);
        }
        __syncthreads();

        // ---- Phase B3: scale v2 in place ----------------------------------
        {
            float inv = s_inv[p_l];
            const int cbase = q_l * 16;
#pragma unroll
            for (int cc = 0; cc < 16; ++cc)
                s_v2[(cbase + cc) * PAD + p_l] *= inv;
        }
        __syncthreads();

        // ---- Phase C: packed-pair masked accumulation ---------------------
        {
            const float* mfb = &s_mf[kg * 32 * 12];
            const float* pv1 = &s_v1[c * PAD];
            const float* pv2 = &s_v2[c * PAD];
#pragma unroll 4
            for (int pp = 0; pp < 32; ++pp) {
                u64 va2 = *(const u64*)(pv1 + 2 * pp);
                u64 vb2 = *(const u64*)(pv2 + 2 * pp);
                float4 mA = *(const float4*)(mfb + pp * 12);
                float4 mB = *(const float4*)(mfb + pp * 12 + 4);
                u64    m4 = *(const u64*)  (mfb + pp * 12 + 8);
                u64 m0 = pk(mA.x, mA.y);
                u64 m1 = pk(mA.z, mA.w);
                u64 m2 = pk(mB.x, mB.y);
                u64 m3 = pk(mB.z, mB.w);
                FMA2(acc1[0], m0, va2); FMA2(acc2[0], m0, vb2);
                FMA2(acc1[1], m1, va2); FMA2(acc2[1], m1, vb2);
                FMA2(acc1[2], m2, va2); FMA2(acc2[2], m2, vb2);
                FMA2(acc1[3], m3, va2); FMA2(acc2[3], m3, vb2);
                FMA2(acc1[4], m4, va2); FMA2(acc2[4], m4, vb2);
            }
        }

        // counts + sq: 20 threads, packed pairs
        if (tid < K) {
            const int mykg = tid & 3;
            const int jj   = tid >> 2;
            const float* mfb = &s_mf[mykg * 32 * 12 + 2 * jj];
#pragma unroll 8
            for (int pp = 0; pp < 32; ++pp) {
                u64 m   = *(const u64*)(mfb + pp * 12);
                u64 s1p = *(const u64*)(&s_s1[2 * pp]);
                ADD2(cnt2, m);
                FMA2(sq2, m, s1p);
            }
        }
    }

    // ---- write per-block partials ----------------------------------------
    float* base = g_part + (size_t)blockIdx.x * PART_STRIDE;
#pragma unroll
    for (int j = 0; j < 5; ++j) {
        int k = kg + 4 * j;
        float lo, hi;
        upk(lo, hi, acc1[j]);
        base[OFF_SUM1 + k * C + c] = lo + hi;
        upk(lo, hi, acc2[j]);
        base[OFF_USUM + k * C + c] = lo + hi;
    }
    if (tid < K) {
        float lo, hi;
        upk(lo, hi, cnt2);
        base[OFF_CNT + tid] = lo + hi;
        upk(lo, hi, sq2);
        base[OFF_SQ + tid] = lo + hi;
    }
}

// ---------------------------------------------------------------------------
// Reduce: coalesced. Block handles 16 consecutive partial indices; 16 thread-
// rows sweep the 512 block-partials; fixed-order smem combine (deterministic).
// ---------------------------------------------------------------------------
#define RED_BLOCKS ((PART_STRIDE + 15) / 16)   // 163

__global__ void __launch_bounds__(256, 8)
reduce_partials()
{
    __shared__ float s[16][17];
    const int il = threadIdx.x & 15;
    const int br = threadIdx.x >> 4;           // 0..15
    const int i  = blockIdx.x * 16 + il;

    float acc = 0.f;
    if (i < PART_STRIDE) {
#pragma unroll 4
        for (int j = 0; j < NBLOCK / 16; ++j) {      // 32 fixed-order loads
            int b = br + 16 * j;
            acc += g_part[(size_t)b * PART_STRIDE + i];
        }
    }
    s[br][il] = acc;
    __syncthreads();

    if (threadIdx.x < 16) {
        const int ii = blockIdx.x * 16 + threadIdx.x;
        if (ii < PART_STRIDE) {
            float t = 0.f;
#pragma unroll
            for (int b = 0; b < 16; ++b) t += s[b][threadIdx.x];
            g_red[ii] = t;
        }
    }
}

// ---------------------------------------------------------------------------
// Finalize: small math on reduced sums. Single block, 512 threads.
// ---------------------------------------------------------------------------
__global__ void __launch_bounds__(512, 1)
finalize(const int* __restrict__ labels, float* __restrict__ out)
{
    __shared__ float S[PART_STRIDE];
    __shared__ float m1n[K * C];
    __shared__ float simm[K * K];
    __shared__ float stdv[K];

    const int tid = threadIdx.x;

    for (int i = tid; i < PART_STRIDE; i += 512) S[i] = g_red[i];
    __syncthreads();

    if (tid < K) {
        const int k = tid;
        float cnt = S[OFF_CNT + k];
        float ssum = 0.f;
        for (int cc = 0; cc < C; ++cc) ssum += S[OFF_SUM1 + k * C + cc];
        float n_elem = cnt * (float)C;
        float em  = ssum / n_elem;
        float var = (S[OFF_SQ + k] - n_elem * em * em) / (n_elem - 1.0f);
        stdv[k] = sqrtf(fmaxf(var, 0.0f));

        float nrm2 = 0.f;
        for (int cc = 0; cc < C; ++cc) {
            float m = S[OFF_SUM1 + k * C + cc] / cnt;
            m1n[k * C + cc] = m;
            nrm2 = fmaf(m, m, nrm2);
        }
        float inv = 1.0f / fmaxf(sqrtf(nrm2), EPS);
        for (int cc = 0; cc < C; ++cc) m1n[k * C + cc] *= inv;
        for (int cc = 0; cc < C; ++cc) S[OFF_USUM + k * C + cc] /= cnt;
    }
    __syncthreads();

    if (tid < K * K) {
        int i = tid / K;
        int j = tid % K;
        float d = 0.f;
#pragma unroll 8
        for (int cc = 0; cc < C; ++cc)
            d = fmaf(m1n[i * C + cc], S[OFF_USUM + j * C + cc], d);
        simm[i * K + j] = d;
    }
    __syncthreads();

    if (tid == 0) {
        int cls[K];
        for (int i = 0; i < K; ++i) cls[i] = labels[i];

        float inst[NUM_CLASSES]  = {};
        float clsim[NUM_CLASSES] = {};
        float clstd[NUM_CLASSES] = {};
        float csum[NUM_CLASSES]  = {};
        float negsum = 0.f;
        int   negcnt = 0;

        for (int i = 0; i < K; ++i) {
            int ci = cls[i];
            inst[ci]  += simm[i * K + i];
            clstd[ci] += stdv[i];
            csum[ci]  += 1.0f;
            for (int j = 0; j < K; ++j) {
                if (j == i) continue;
                if (cls[j] == ci) clsim[ci] += simm[i * K + j];
                else { negsum += simm[i * K + j]; negcnt++; }
            }
        }
        for (int cc = 0; cc < NUM_CLASSES; ++cc) {
            if (csum[cc] > 1.0f) {
                inst[cc]  /= csum[cc];
                clsim[cc] /= csum[cc] * (csum[cc] - 1.0f);
                clstd[cc] /= csum[cc];
            }
        }
        for (int cc = 0; cc < NUM_CLASSES; ++cc) {
            out[cc]      = inst[cc];
            out[11 + cc] = clsim[cc];
            out[23 + cc] = clstd[cc];
        }
        out[22] = negsum / (float)negcnt;
    }
}

extern "C" void kernel_launch(void* const* d_in, const int* in_sizes, int n_in,
                              void* d_out, int out_size)
{
    const float* v1     = (const float*)d_in[0];
    const float* v2     = (const float*)d_in[1];
    const int*   labels = (const int*)d_in[2];
    const int*   masks  = (const int*)d_in[3];
    float* out = (float*)d_out;

    main_pass<<<NBLOCK, 256>>>(v1, v2, masks);
    reduce_partials<<<RED_BLOCKS, 256>>>();
    finalize<<<1, 512>>>(labels, out);
}

// round 8
// speedup vs baseline: 1.4231x; 1.4231x over previous
#include <cuda_runtime.h>
#include <math.h>
#include <stdint.h>

#define C 64
#define P (512 * 512)
#define K 20
#define NUM_CLASSES 11
#define EPS 1e-8f

#define NBLOCK 512
#define PPB 512                 // pixels per block
#define TK 64                   // pixels per MMA tile
#define NT (PPB / TK)           // 8 tiles

#define ASTRIDE 68              // padded row stride (floats): banks 4g+tg distinct
#define A_FLOATS (128 * ASTRIDE)
#define RED_FLOATS 2048         // aliased region: s_red1|s_red2 (2048) / s_bf (1632)
#define DYN_SZ ((A_FLOATS + RED_FLOATS) * 4)   // 43008 B < 48K default limit

// partials: sum1[20][64] | usum[20][64] | cnt[20] | sq[20]
#define PART_STRIDE 2600
#define OFF_SUM1 0
#define OFF_USUM 1280
#define OFF_CNT 2560
#define OFF_SQ 2580

static __device__ float g_part[NBLOCK * PART_STRIDE];
static __device__ float g_red[PART_STRIDE];

// tf32 m16n8k8 row.col MMA (sm_80+, works at compute_100)
__device__ __forceinline__ void mma_tf32(float& d0, float& d1, float& d2, float& d3,
                                         uint32_t a0, uint32_t a1, uint32_t a2, uint32_t a3,
                                         uint32_t b0, uint32_t b1)
{
    asm volatile(
        "mma.sync.aligned.m16n8k8.row.col.f32.tf32.tf32.f32 "
        "{%0,%1,%2,%3}, {%4,%5,%6,%7}, {%8,%9}, {%0,%1,%2,%3};"
        : "+f"(d0), "+f"(d1), "+f"(d2), "+f"(d3)
        : "r"(a0), "r"(a1), "r"(a2), "r"(a3), "r"(b0), "r"(b1));
}

__device__ __forceinline__ void hi_lo(float v, uint32_t& h, uint32_t& l)
{
    uint32_t hu = __float_as_uint(v) & 0xFFFFE000u;   // tf32 truncation (10-bit mant)
    h = hu;
    l = __float_as_uint(v - __uint_as_float(hu));     // residual
}

// ---------------------------------------------------------------------------
// Main pass: warp-tiled tf32 MMA.  D[128][24] = A · B^T over K=512 pixels.
// A rows 0-63 = v1 channels, 64-127 = per-pixel-normalized v2 channels.
// B rows = instance masks (0/1), rows 20-23 zero (s_mb bits 20+ unset).
// s_red1/s_red2 (Phase A-B) alias s_bf (Phase C-D): disjoint lifetimes,
// separated by __syncthreads.
// ---------------------------------------------------------------------------
__global__ void __launch_bounds__(256, 2)
main_pass(const float* __restrict__ v1g,
          const float* __restrict__ v2g,
          const int* __restrict__ masks)
{
    extern __shared__ float dyn[];
    float* s_a    = dyn;                       // [128][68]
    float* s_red1 = dyn + A_FLOATS;            // [1024]   (Phase A-B)
    float* s_red2 = dyn + A_FLOATS + 1024;     // [1024]   (Phase A-B)
    float* s_bf   = dyn + A_FLOATS;            // [24][68] (Phase C-D, aliases s_red)

    __shared__ float s_s1[64];
    __shared__ float s_inv[64];
    __shared__ int   s_mb[64];

    const int tid = threadIdx.x;
    const int wid = tid >> 5;
    const int lane = tid & 31;
    const int g  = lane >> 2;     // 0..7
    const int tg = lane & 3;      // 0..3
    const int f4 = tid & 15;      // pixel quad
    const int cr = tid >> 4;      // channel row group

    float acc[3][4];
#pragma unroll
    for (int nt = 0; nt < 3; ++nt)
#pragma unroll
        for (int q = 0; q < 4; ++q) acc[nt][q] = 0.f;

    float cntAcc = 0.f, sqAcc = 0.f;
    const size_t p0base = (size_t)blockIdx.x * PPB;
    const int rowA0 = 16 * wid + g;       // fragment M-row (global), +8 for second

    for (int t = 0; t < NT; ++t) {
        const size_t p0 = p0base + (size_t)t * TK;
        __syncthreads();   // previous tile's MMA reads done (frees s_a and s_bf)

        // ---- Phase A: stage v1 raw, v2 in regs, squares, masks ------------
        float4 pp1 = make_float4(0.f, 0.f, 0.f, 0.f);
        float4 pp2 = make_float4(0.f, 0.f, 0.f, 0.f);
        float4 bv[4];
#pragma unroll
        for (int i = 0; i < 4; ++i) {
            int c = cr + 16 * i;
            float4 a = *(const float4*)(v1g + (size_t)c * P + p0 + 4 * f4);
            pp1.x = fmaf(a.x, a.x, pp1.x); pp1.y = fmaf(a.y, a.y, pp1.y);
            pp1.z = fmaf(a.z, a.z, pp1.z); pp1.w = fmaf(a.w, a.w, pp1.w);
            *(float4*)&s_a[c * ASTRIDE + 4 * f4] = a;

            bv[i] = *(const float4*)(v2g + (size_t)c * P + p0 + 4 * f4);
            pp2.x = fmaf(bv[i].x, bv[i].x, pp2.x); pp2.y = fmaf(bv[i].y, bv[i].y, pp2.y);
            pp2.z = fmaf(bv[i].z, bv[i].z, pp2.z); pp2.w = fmaf(bv[i].w, bv[i].w, pp2.w);
        }
        *(float4*)&s_red1[tid * 4] = pp1;
        *(float4*)&s_red2[tid * 4] = pp2;

        if (tid < TK) {
            int mb = 0;
#pragma unroll
            for (int k = 0; k < K; ++k)
                mb |= (masks[(size_t)k * P + p0 + tid] & 1) << k;
            s_mb[tid] = mb;
        }
        __syncthreads();

        // ---- Phase B: reduce per-pixel norms ------------------------------
        if (tid < TK) {
            int q = tid >> 2, cm = tid & 3;
            float s1 = 0.f, s2 = 0.f;
#pragma unroll
            for (int r = 0; r < 16; ++r) {
                s1 += s_red1[(r * 16 + q) * 4 + cm];
                s2 += s_red2[(r * 16 + q) * 4 + cm];
            }
            s_s1[tid]  = s1;
            s_inv[tid] = 1.0f / fmaxf(sqrtf(s2), EPS);
        }
        __syncthreads();

        // ---- Phase C: scale v2 -> s_a rows 64-127; build B tile; cnt/sq ---
        // (s_bf writes clobber s_red — safe, Phase B complete)
        {
            float4 iv = *(const float4*)&s_inv[4 * f4];
#pragma unroll
            for (int i = 0; i < 4; ++i) {
                int c = cr + 16 * i;
                float4 bn;
                bn.x = bv[i].x * iv.x; bn.y = bv[i].y * iv.y;
                bn.z = bv[i].z * iv.z; bn.w = bv[i].w * iv.w;
                *(float4*)&s_a[(64 + c) * ASTRIDE + 4 * f4] = bn;
            }
        }
#pragma unroll
        for (int r = 0; r < 6; ++r) {
            int e = tid + 256 * r;      // 0..1535 -> all 24 rows x 64 cols
            int n = e >> 6, p = e & 63;
            s_bf[n * ASTRIDE + p] = (float)((s_mb[p] >> n) & 1);  // 0 for n>=20
        }
        if (tid < K) {
#pragma unroll 8
            for (int p = 0; p < TK; ++p)
                if ((s_mb[p] >> tid) & 1) { cntAcc += 1.0f; sqAcc += s_s1[p]; }
        }
        __syncthreads();

        // ---- Phase D: MMA over 8 k-steps ----------------------------------
#pragma unroll
        for (int s = 0; s < 8; ++s) {
            int c0 = 8 * s + tg;
            int c1 = c0 + 4;
            float ra0 = s_a[rowA0 * ASTRIDE + c0];
            float ra1 = s_a[(rowA0 + 8) * ASTRIDE + c0];
            float ra2 = s_a[rowA0 * ASTRIDE + c1];
            float ra3 = s_a[(rowA0 + 8) * ASTRIDE + c1];
            uint32_t h0, l0, h1, l1, h2, l2, h3, l3;
            hi_lo(ra0, h0, l0); hi_lo(ra1, h1, l1);
            hi_lo(ra2, h2, l2); hi_lo(ra3, h3, l3);
#pragma unroll
            for (int nt = 0; nt < 3; ++nt) {
                int n0 = 8 * nt + g;
                uint32_t b0 = __float_as_uint(s_bf[n0 * ASTRIDE + c0]);
                uint32_t b1 = __float_as_uint(s_bf[n0 * ASTRIDE + c1]);
                mma_tf32(acc[nt][0], acc[nt][1], acc[nt][2], acc[nt][3],
                         h0, h1, h2, h3, b0, b1);
                mma_tf32(acc[nt][0], acc[nt][1], acc[nt][2], acc[nt][3],
                         l0, l1, l2, l3, b0, b1);
            }
        }
    }

    // ---- epilogue: accumulators -> per-block partials ---------------------
    float* base = g_part + (size_t)blockIdx.x * PART_STRIDE;
    {
        int m0 = rowA0;           // 16w+g
        int m1 = rowA0 + 8;
        int off0 = (m0 < 64) ? (OFF_SUM1 + m0) : (OFF_USUM + (m0 - 64));
        int off1 = (m1 < 64) ? (OFF_SUM1 + m1) : (OFF_USUM + (m1 - 64));
#pragma unroll
        for (int nt = 0; nt < 3; ++nt) {
            int n0 = 8 * nt + 2 * tg;
            if (n0 < K)     base[off0 + n0 * C]       = acc[nt][0];
            if (n0 + 1 < K) base[off0 + (n0 + 1) * C] = acc[nt][1];
            if (n0 < K)     base[off1 + n0 * C]       = acc[nt][2];
            if (n0 + 1 < K) base[off1 + (n0 + 1) * C] = acc[nt][3];
        }
    }
    if (tid < K) {
        base[OFF_CNT + tid] = cntAcc;
        base[OFF_SQ  + tid] = sqAcc;
    }
}

// ---------------------------------------------------------------------------
// Reduce: coalesced, deterministic fixed-order.
// ---------------------------------------------------------------------------
#define RED_BLOCKS ((PART_STRIDE + 15) / 16)

__global__ void __launch_bounds__(256, 8)
reduce_partials()
{
    __shared__ float s[16][17];
    const int il = threadIdx.x & 15;
    const int br = threadIdx.x >> 4;
    const int i  = blockIdx.x * 16 + il;

    float acc = 0.f;
    if (i < PART_STRIDE) {
#pragma unroll 4
        for (int j = 0; j < NBLOCK / 16; ++j)
            acc += g_part[(size_t)(br + 16 * j) * PART_STRIDE + i];
    }
    s[br][il] = acc;
    __syncthreads();

    if (threadIdx.x < 16) {
        const int ii = blockIdx.x * 16 + threadIdx.x;
        if (ii < PART_STRIDE) {
            float t = 0.f;
#pragma unroll
            for (int b = 0; b < 16; ++b) t += s[b][threadIdx.x];
            g_red[ii] = t;
        }
    }
}

// ---------------------------------------------------------------------------
// Finalize: parallel small math (deterministic).
// ---------------------------------------------------------------------------
__global__ void __launch_bounds__(512, 1)
finalize(const int* __restrict__ labels, float* __restrict__ out)
{
    __shared__ float S[PART_STRIDE];
    __shared__ float m1n[K * C];
    __shared__ float simm[K * K];
    __shared__ float stdv[K];
    __shared__ int   s_cls[K];

    const int tid = threadIdx.x;

    for (int i = tid; i < PART_STRIDE; i += 512) S[i] = g_red[i];
    if (tid < K) s_cls[tid] = labels[tid];
    __syncthreads();

    if (tid < K) {
        const int k = tid;
        float cnt = S[OFF_CNT + k];
        float rc  = 1.0f / cnt;
        float ssum = 0.f;
        for (int cc = 0; cc < C; ++cc) ssum += S[OFF_SUM1 + k * C + cc];
        float n_elem = cnt * (float)C;
        float em  = ssum / n_elem;
        float var = (S[OFF_SQ + k] - n_elem * em * em) / (n_elem - 1.0f);
        stdv[k] = sqrtf(fmaxf(var, 0.0f));

        float nrm2 = 0.f;
        for (int cc = 0; cc < C; ++cc) {
            float m = S[OFF_SUM1 + k * C + cc] * rc;
            m1n[k * C + cc] = m;
            nrm2 = fmaf(m, m, nrm2);
        }
        float inv = 1.0f / fmaxf(sqrtf(nrm2), EPS);
        for (int cc = 0; cc < C; ++cc) m1n[k * C + cc] *= inv;
        for (int cc = 0; cc < C; ++cc) S[OFF_USUM + k * C + cc] *= rc;
    }
    __syncthreads();

    if (tid < K * K) {
        int i = tid / K;
        int j = tid % K;
        float d = 0.f;
#pragma unroll 8
        for (int cc = 0; cc < C; ++cc)
            d = fmaf(m1n[i * C + cc], S[OFF_USUM + j * C + cc], d);
        simm[i * K + j] = d;
    }
    __syncthreads();

    if (tid < 32) {
        float ns = 0.f, nc = 0.f;
        for (int e = tid; e < K * K; e += 32) {
            int i = e / K, j = e % K;
            if (s_cls[i] != s_cls[j]) { ns += simm[e]; nc += 1.0f; }
        }
#pragma unroll
        for (int off = 16; off > 0; off >>= 1) {
            ns += __shfl_xor_sync(0xFFFFFFFFu, ns, off);
            nc += __shfl_xor_sync(0xFFFFFFFFu, nc, off);
        }
        if (tid == 0) out[22] = ns / nc;
    } else if (tid >= 64 && tid < 64 + NUM_CLASSES) {
        const int cl = tid - 64;
        float inst = 0.f, st = 0.f, cs = 0.f, cnt = 0.f;
        for (int i = 0; i < K; ++i) {
            if (s_cls[i] == cl) {
                inst += simm[i * K + i];
                st   += stdv[i];
                cnt  += 1.0f;
                for (int j = 0; j < K; ++j)
                    if (j != i && s_cls[j] == cl) cs += simm[i * K + j];
            }
        }
        if (cnt > 1.0f) {
            inst /= cnt;
            cs   /= cnt * (cnt - 1.0f);
            st   /= cnt;
        }
        out[cl]      = inst;
        out[11 + cl] = cs;
        out[23 + cl] = st;
    }
}

extern "C" void kernel_launch(void* const* d_in, const int* in_sizes, int n_in,
                              void* d_out, int out_size)
{
    const float* v1     = (const float*)d_in[0];
    const float* v2     = (const float*)d_in[1];
    const int*   labels = (const int*)d_in[2];
    const int*   masks  = (const int*)d_in[3];
    float* out = (float*)d_out;

    main_pass<<<NBLOCK, 256, DYN_SZ>>>(v1, v2, masks);
    reduce_partials<<<RED_BLOCKS, 256>>>();
    finalize<<<1, 512>>>(labels, out);
}

// round 9
// speedup vs baseline: 1.6846x; 1.1838x over previous
#include <cuda_runtime.h>
#include <math.h>
#include <stdint.h>

#define C 64
#define P (512 * 512)
#define K 20
#define NUM_CLASSES 11
#define EPS 1e-8f

#define NBLOCK 256
#define PPB (P / NBLOCK)        // 1024 pixels per block
#define TK 64                   // pixels per MMA tile
#define NT (PPB / TK)           // 16 tiles

#define ASTRIDE 68              // padded row stride (floats): banks 4g+tg distinct
#define A_FLOATS (128 * ASTRIDE)
#define RED_FLOATS 2048         // aliased: s_red1|s_red2 (2048) / s_bf (24*68=1632)
#define DYN_SZ ((A_FLOATS + RED_FLOATS) * 4)   // 43008 B < 48K default limit

// partials: sum1[20][64] | usum[20][64] | cnt[20] | sq[20]
#define PART_STRIDE 2600
#define OFF_SUM1 0
#define OFF_USUM 1280
#define OFF_CNT 2560
#define OFF_SQ 2580

static __device__ float g_part[NBLOCK * PART_STRIDE];
static __device__ float g_red[PART_STRIDE];

// tf32 m16n8k8 row.col MMA (sm_80+, works at compute_100)
__device__ __forceinline__ void mma_tf32(float& d0, float& d1, float& d2, float& d3,
                                         uint32_t a0, uint32_t a1, uint32_t a2, uint32_t a3,
                                         uint32_t b0, uint32_t b1)
{
    asm volatile(
        "mma.sync.aligned.m16n8k8.row.col.f32.tf32.tf32.f32 "
        "{%0,%1,%2,%3}, {%4,%5,%6,%7}, {%8,%9}, {%0,%1,%2,%3};"
        : "+f"(d0), "+f"(d1), "+f"(d2), "+f"(d3)
        : "r"(a0), "r"(a1), "r"(a2), "r"(a3), "r"(b0), "r"(b1));
}

__device__ __forceinline__ void hi_lo(float v, uint32_t& h, uint32_t& l)
{
    uint32_t hu = __float_as_uint(v) & 0xFFFFE000u;   // tf32 truncation
    h = hu;
    l = __float_as_uint(v - __uint_as_float(hu));     // residual
}

// ---------------------------------------------------------------------------
// Main pass: warp-tiled tf32 MMA, software-pipelined.
// D[128][24] = A · B^T over K = 1024 pixels (16 tiles of 64).
// A rows 0-63 = v1 channels, 64-127 = normalized v2 channels.
// B rows = masks (0/1), rows 20-23 zero.
// Prefetch: v1/v2 quads for tile t+1 issued end of Phase A(t); mask ints for
// tile t+1 issued end of Phase C(t). s_red (A-B) aliases s_bf (C-D).
// ---------------------------------------------------------------------------
__global__ void __launch_bounds__(256, 2)
main_pass(const float* __restrict__ v1g,
          const float* __restrict__ v2g,
          const int* __restrict__ masks)
{
    extern __shared__ float dyn[];
    float* s_a    = dyn;                       // [128][68]
    float* s_red1 = dyn + A_FLOATS;            // [1024]   (Phase A-B)
    float* s_red2 = dyn + A_FLOATS + 1024;     // [1024]   (Phase A-B)
    float* s_bf   = dyn + A_FLOATS;            // [24][68] (Phase C-D, aliases s_red)

    __shared__ float s_s1[64];
    __shared__ float s_inv[64];

    const int tid = threadIdx.x;
    const int wid = tid >> 5;
    const int lane = tid & 31;
    const int g  = lane >> 2;     // 0..7
    const int tg = lane & 3;      // 0..3
    const int f4 = tid & 15;      // pixel quad
    const int cr = tid >> 4;      // channel row group

    // mask-element mapping: element e = tid + 256*r -> row k = e>>6, pixel p = e&63
    int mk[5], mp[5];
#pragma unroll
    for (int r = 0; r < 5; ++r) {
        int e = tid + 256 * r;
        mk[r] = e >> 6;
        mp[r] = e & 63;
    }

    float acc[3][4];
#pragma unroll
    for (int nt = 0; nt < 3; ++nt)
#pragma unroll
        for (int q = 0; q < 4; ++q) acc[nt][q] = 0.f;

    float cntAcc = 0.f, sqAcc = 0.f;
    const size_t p0base = (size_t)blockIdx.x * PPB;
    const int rowA0 = 16 * wid + g;

    // ---- prologue: load tile 0 -------------------------------------------
    float4 av[4], bv[4];
    int mreg[5];
#pragma unroll
    for (int i = 0; i < 4; ++i) {
        int c = cr + 16 * i;
        av[i] = *(const float4*)(v1g + (size_t)c * P + p0base + 4 * f4);
        bv[i] = *(const float4*)(v2g + (size_t)c * P + p0base + 4 * f4);
    }
#pragma unroll
    for (int r = 0; r < 5; ++r)
        mreg[r] = masks[(size_t)mk[r] * P + p0base + mp[r]];

    for (int t = 0; t < NT; ++t) {
        const size_t p0 = p0base + (size_t)t * TK;
        const size_t p1 = p0 + TK;
        __syncthreads();   // prev tile's MMA/cnt reads done: s_a, s_bf free

        // ---- Phase A: consume av/bv -> STS raw + squares; prefetch v ------
        float4 pp1 = make_float4(0.f, 0.f, 0.f, 0.f);
        float4 pp2 = make_float4(0.f, 0.f, 0.f, 0.f);
#pragma unroll
        for (int i = 0; i < 4; ++i) {
            int c = cr + 16 * i;
            float4 a = av[i];
            pp1.x = fmaf(a.x, a.x, pp1.x); pp1.y = fmaf(a.y, a.y, pp1.y);
            pp1.z = fmaf(a.z, a.z, pp1.z); pp1.w = fmaf(a.w, a.w, pp1.w);
            *(float4*)&s_a[c * ASTRIDE + 4 * f4] = a;
            float4 b = bv[i];
            pp2.x = fmaf(b.x, b.x, pp2.x); pp2.y = fmaf(b.y, b.y, pp2.y);
            pp2.z = fmaf(b.z, b.z, pp2.z); pp2.w = fmaf(b.w, b.w, pp2.w);
            *(float4*)&s_a[(64 + c) * ASTRIDE + 4 * f4] = b;   // raw v2, rescaled in C
        }
        *(float4*)&s_red1[tid * 4] = pp1;
        *(float4*)&s_red2[tid * 4] = pp2;

        if (t + 1 < NT) {
#pragma unroll
            for (int i = 0; i < 4; ++i) {
                int c = cr + 16 * i;
                av[i] = *(const float4*)(v1g + (size_t)c * P + p1 + 4 * f4);
                bv[i] = *(const float4*)(v2g + (size_t)c * P + p1 + 4 * f4);
            }
        }
        __syncthreads();

        // ---- Phase B: reduce per-pixel norms (64 threads) -----------------
        if (tid < TK) {
            int q = tid >> 2, cm = tid & 3;
            float s1 = 0.f, s2 = 0.f;
#pragma unroll
            for (int r = 0; r < 16; ++r) {
                s1 += s_red1[(r * 16 + q) * 4 + cm];
                s2 += s_red2[(r * 16 + q) * 4 + cm];
            }
            s_s1[tid]  = s1;
            s_inv[tid] = 1.0f / fmaxf(sqrtf(s2), EPS);
        }
        __syncthreads();

        // ---- Phase C: rescale v2 in place; build B tile; prefetch masks ---
        {
            float4 iv = *(const float4*)&s_inv[4 * f4];
#pragma unroll
            for (int i = 0; i < 4; ++i) {
                int c = cr + 16 * i;
                float4 b = *(const float4*)&s_a[(64 + c) * ASTRIDE + 4 * f4];
                b.x *= iv.x; b.y *= iv.y; b.z *= iv.z; b.w *= iv.w;
                *(float4*)&s_a[(64 + c) * ASTRIDE + 4 * f4] = b;
            }
        }
#pragma unroll
        for (int r = 0; r < 5; ++r)
            s_bf[mk[r] * ASTRIDE + mp[r]] = (float)(mreg[r] & 1);
        // zero pad rows 20..23 (aliased region clobbered every tile)
        s_bf[(20 + (tid >> 6)) * ASTRIDE + (tid & 63)] = 0.f;

        if (t + 1 < NT) {
#pragma unroll
            for (int r = 0; r < 5; ++r)
                mreg[r] = masks[(size_t)mk[r] * P + p1 + mp[r]];
        }
        __syncthreads();

        // ---- Phase D: MMA over 8 k-steps; cnt/sq on warp 0 ---------------
#pragma unroll
        for (int s = 0; s < 8; ++s) {
            int c0 = 8 * s + tg;
            int c1 = c0 + 4;
            float ra0 = s_a[rowA0 * ASTRIDE + c0];
            float ra1 = s_a[(rowA0 + 8) * ASTRIDE + c0];
            float ra2 = s_a[rowA0 * ASTRIDE + c1];
            float ra3 = s_a[(rowA0 + 8) * ASTRIDE + c1];
            uint32_t h0, l0, h1, l1, h2, l2, h3, l3;
            hi_lo(ra0, h0, l0); hi_lo(ra1, h1, l1);
            hi_lo(ra2, h2, l2); hi_lo(ra3, h3, l3);
#pragma unroll
            for (int nt = 0; nt < 3; ++nt) {
                int n0 = 8 * nt + g;
                uint32_t b0 = __float_as_uint(s_bf[n0 * ASTRIDE + c0]);
                uint32_t b1 = __float_as_uint(s_bf[n0 * ASTRIDE + c1]);
                mma_tf32(acc[nt][0], acc[nt][1], acc[nt][2], acc[nt][3],
                         h0, h1, h2, h3, b0, b1);
                mma_tf32(acc[nt][0], acc[nt][1], acc[nt][2], acc[nt][3],
                         l0, l1, l2, l3, b0, b1);
            }
        }
        if (tid < K) {
            float c0 = 0.f, s0 = 0.f;
#pragma unroll 8
            for (int p = 0; p < TK; ++p) {
                float m = s_bf[tid * ASTRIDE + p];
                c0 += m;
                s0 = fmaf(m, s_s1[p], s0);
            }
            cntAcc += c0;
            sqAcc  += s0;
        }
    }

    // ---- epilogue: accumulators -> per-block partials ---------------------
    float* base = g_part + (size_t)blockIdx.x * PART_STRIDE;
    {
        int m0 = rowA0;
        int m1 = rowA0 + 8;
        int off0 = (m0 < 64) ? (OFF_SUM1 + m0) : (OFF_USUM + (m0 - 64));
        int off1 = (m1 < 64) ? (OFF_SUM1 + m1) : (OFF_USUM + (m1 - 64));
#pragma unroll
        for (int nt = 0; nt < 3; ++nt) {
            int n0 = 8 * nt + 2 * tg;
            if (n0 < K)     base[off0 + n0 * C]       = acc[nt][0];
            if (n0 + 1 < K) base[off0 + (n0 + 1) * C] = acc[nt][1];
            if (n0 < K)     base[off1 + n0 * C]       = acc[nt][2];
            if (n0 + 1 < K) base[off1 + (n0 + 1) * C] = acc[nt][3];
        }
    }
    if (tid < K) {
        base[OFF_CNT + tid] = cntAcc;
        base[OFF_SQ  + tid] = sqAcc;
    }
}

// ---------------------------------------------------------------------------
// Reduce: coalesced, deterministic fixed-order.
// ---------------------------------------------------------------------------
#define RED_BLOCKS ((PART_STRIDE + 15) / 16)

__global__ void __launch_bounds__(256, 8)
reduce_partials()
{
    __shared__ float s[16][17];
    const int il = threadIdx.x & 15;
    const int br = threadIdx.x >> 4;
    const int i  = blockIdx.x * 16 + il;

    float acc = 0.f;
    if (i < PART_STRIDE) {
#pragma unroll 4
        for (int j = 0; j < NBLOCK / 16; ++j)
            acc += g_part[(size_t)(br + 16 * j) * PART_STRIDE + i];
    }
    s[br][il] = acc;
    __syncthreads();

    if (threadIdx.x < 16) {
        const int ii = blockIdx.x * 16 + threadIdx.x;
        if (ii < PART_STRIDE) {
            float t = 0.f;
#pragma unroll
            for (int b = 0; b < 16; ++b) t += s[b][threadIdx.x];
            g_red[ii] = t;
        }
    }
}

// ---------------------------------------------------------------------------
// Finalize: parallel small math (deterministic).
// ---------------------------------------------------------------------------
__global__ void __launch_bounds__(512, 1)
finalize(const int* __restrict__ labels, float* __restrict__ out)
{
    __shared__ float S[PART_STRIDE];
    __shared__ float m1n[K * C];
    __shared__ float simm[K * K];
    __shared__ float stdv[K];
    __shared__ int   s_cls[K];

    const int tid = threadIdx.x;

    for (int i = tid; i < PART_STRIDE; i += 512) S[i] = g_red[i];
    if (tid < K) s_cls[tid] = labels[tid];
    __syncthreads();

    if (tid < K) {
        const int k = tid;
        float cnt = S[OFF_CNT + k];
        float rc  = 1.0f / cnt;
        float ssum = 0.f;
        for (int cc = 0; cc < C; ++cc) ssum += S[OFF_SUM1 + k * C + cc];
        float n_elem = cnt * (float)C;
        float em  = ssum / n_elem;
        float var = (S[OFF_SQ + k] - n_elem * em * em) / (n_elem - 1.0f);
        stdv[k] = sqrtf(fmaxf(var, 0.0f));

        float nrm2 = 0.f;
        for (int cc = 0; cc < C; ++cc) {
            float m = S[OFF_SUM1 + k * C + cc] * rc;
            m1n[k * C + cc] = m;
            nrm2 = fmaf(m, m, nrm2);
        }
        float inv = 1.0f / fmaxf(sqrtf(nrm2), EPS);
        for (int cc = 0; cc < C; ++cc) m1n[k * C + cc] *= inv;
        for (int cc = 0; cc < C; ++cc) S[OFF_USUM + k * C + cc] *= rc;
    }
    __syncthreads();

    if (tid < K * K) {
        int i = tid / K;
        int j = tid % K;
        float d = 0.f;
#pragma unroll 8
        for (int cc = 0; cc < C; ++cc)
            d = fmaf(m1n[i * C + cc], S[OFF_USUM + j * C + cc], d);
        simm[i * K + j] = d;
    }
    __syncthreads();

    if (tid < 32) {
        float ns = 0.f, nc = 0.f;
        for (int e = tid; e < K * K; e += 32) {
            int i = e / K, j = e % K;
            if (s_cls[i] != s_cls[j]) { ns += simm[e]; nc += 1.0f; }
        }
#pragma unroll
        for (int off = 16; off > 0; off >>= 1) {
            ns += __shfl_xor_sync(0xFFFFFFFFu, ns, off);
            nc += __shfl_xor_sync(0xFFFFFFFFu, nc, off);
        }
        if (tid == 0) out[22] = ns / nc;
    } else if (tid >= 64 && tid < 64 + NUM_CLASSES) {
        const int cl = tid - 64;
        float inst = 0.f, st = 0.f, cs = 0.f, cnt = 0.f;
        for (int i = 0; i < K; ++i) {
            if (s_cls[i] == cl) {
                inst += simm[i * K + i];
                st   += stdv[i];
                cnt  += 1.0f;
                for (int j = 0; j < K; ++j)
                    if (j != i && s_cls[j] == cl) cs += simm[i * K + j];
            }
        }
        if (cnt > 1.0f) {
            inst /= cnt;
            cs   /= cnt * (cnt - 1.0f);
            st   /= cnt;
        }
        out[cl]      = inst;
        out[11 + cl] = cs;
        out[23 + cl] = st;
    }
}

extern "C" void kernel_launch(void* const* d_in, const int* in_sizes, int n_in,
                              void* d_out, int out_size)
{
    const float* v1     = (const float*)d_in[0];
    const float* v2     = (const float*)d_in[1];
    const int*   labels = (const int*)d_in[2];
    const int*   masks  = (const int*)d_in[3];
    float* out = (float*)d_out;

    main_pass<<<NBLOCK, 256, DYN_SZ>>>(v1, v2, masks);
    reduce_partials<<<RED_BLOCKS, 256>>>();
    finalize<<<1, 512>>>(labels, out);
}